// round 15
// baseline (speedup 1.0000x reference)
#include <cuda_runtime.h>
#include <cuda_bf16.h>
#include <math.h>
#include <stdint.h>

#define BATCH 512
#define SEQ   196
#define HID   1024
#define MID   512
#define FOUT  2048
#define NB    100
#define ROWS  (BATCH*SEQ)   // 100352

// Scratch (device globals: no allocation allowed)
__device__ __align__(16) float g_att[ROWS];
__device__ __align__(16) float g_w[BATCH*SEQ];
__device__ __align__(16) float g_ctx[BATCH*HID];
__device__ __align__(16) __nv_bfloat16 g_w1b[MID*HID];

__device__ __forceinline__ unsigned pack_bf16(float lo, float hi) {
    unsigned r; asm("cvt.rn.bf16x2.f32 %0, %1, %2;" : "=r"(r) : "f"(hi), "f"(lo)); return r;
}
__device__ __forceinline__ unsigned f2tf32(float x) {
    unsigned y; asm("cvt.rna.tf32.f32 %0, %1;" : "=r"(y) : "f"(x)); return y;
}
__device__ __forceinline__ uint32_t smem_u32(const void* p) {
    uint32_t a;
    asm("{ .reg .u64 t; cvta.to.shared.u64 t, %1; cvt.u32.u64 %0, t; }" : "=r"(a) : "l"(p));
    return a;
}

// 64B-row swizzle (SW64): XOR bits [5:4] with bits [8:7]
#define SWZ64(o) ((o) ^ (((o) >> 3) & 0x30))

#define STS128U(addr, r0, r1, r2, r3) \
    asm volatile("st.shared.v4.b32 [%0], {%1,%2,%3,%4};" \
                 :: "r"(addr), "r"(r0), "r"(r1), "r"(r2), "r"(r3) : "memory")

#define LDSM_X4(r0, r1, r2, r3, addr) \
    asm volatile("ldmatrix.sync.aligned.m8n8.x4.shared.b16 {%0,%1,%2,%3}, [%4];" \
                 : "=r"(r0), "=r"(r1), "=r"(r2), "=r"(r3) : "r"(addr))

#define MMA_BF16(d, a0, a1, a2, a3, b0, b1) \
    asm volatile("mma.sync.aligned.m16n8k16.row.col.f32.bf16.bf16.f32 " \
                 "{%0,%1,%2,%3},{%4,%5,%6,%7},{%8,%9},{%0,%1,%2,%3};" \
                 : "+f"((d)[0]), "+f"((d)[1]), "+f"((d)[2]), "+f"((d)[3]) \
                 : "r"(a0), "r"(a1), "r"(a2), "r"(a3), "r"(b0), "r"(b1))

// ===========================================================================
// k_pre: zero g_att (25088 float4) + cvt W1 -> bf16 (131072 float4)
// ===========================================================================
__global__ void k_pre(const float* __restrict__ W1) {
    size_t i = (size_t)blockIdx.x * 256 + threadIdx.x;
    if (i < 131072) {
        float4 v = ((const float4*)W1)[i];
        ((uint2*)g_w1b)[i] = make_uint2(pack_bf16(v.x, v.y), pack_bf16(v.z, v.w));
    } else {
        ((float4*)g_att)[i - 131072] = make_float4(0.f, 0.f, 0.f, 0.f);
    }
}

// ===========================================================================
// Kernel B: EXACT champion GEMM (measured ~357us).
// ===========================================================================
#define BKG 32
#define NKT (HID/BKG)   // 32

__global__ __launch_bounds__(256, 2)
void k_mlp_att(const float* __restrict__ x,
               const float* __restrict__ b1,
               const float* __restrict__ W2) {
    __shared__ __align__(1024) char smA[2][128 * 64];
    __shared__ __align__(1024) char smB[2][128 * 64];
    __shared__ float b1s[128], w2s[128], s_part[128];

    const int tid  = threadIdx.x;
    const int lane = tid & 31;
    const int warp = tid >> 5;
    const int colBase = blockIdx.x * 128;     // n tile (fastest-varying)
    const int rowBase = blockIdx.y * 128;     // row tile

    const uint32_t sa0 = smem_u32(&smA[0][0]);
    const uint32_t sa1 = smem_u32(&smA[1][0]);
    const uint32_t sb0 = smem_u32(&smB[0][0]);
    const uint32_t sb1 = smem_u32(&smB[1][0]);

    if (tid < 128) {
        b1s[tid] = b1[colBase + tid];
        w2s[tid] = W2[colBase + tid];
        s_part[tid] = 0.f;
    }

    const int wm = warp & 3, wn = warp >> 2;
    const int mBase = wm * 32, nBase = wn * 64;
    const int g = lane >> 2, t = lane & 3;

    const int aRow = mBase + (lane & 15);
    const int aKb  = (lane >> 4) * 16;
    const int bRow = nBase + (lane & 7) + ((lane >> 4) * 8);
    const int bKb  = ((lane >> 3) & 1) * 16;

    uint32_t aOff[2][2], bOff[4][2];
    #pragma unroll
    for (int mi = 0; mi < 2; mi++)
        #pragma unroll
        for (int ks = 0; ks < 2; ks++)
            aOff[mi][ks] = SWZ64((uint32_t)((aRow + mi * 16) * 64 + ks * 32 + aKb));
    #pragma unroll
    for (int nj = 0; nj < 4; nj++)
        #pragma unroll
        for (int ks = 0; ks < 2; ks++)
            bOff[nj][ks] = SWZ64((uint32_t)((bRow + nj * 16) * 64 + ks * 32 + bKb));

    float acc[2][8][4];
    #pragma unroll
    for (int mi = 0; mi < 2; mi++)
        #pragma unroll
        for (int ni = 0; ni < 8; ni++)
            #pragma unroll
            for (int q = 0; q < 4; q++) acc[mi][ni][q] = 0.f;

    const int arow0 = tid >> 2;
    const int ac8   = (tid & 3) * 8;
    auto ldA = [&](int kc, float4* st) {
        const int k0 = kc * BKG;
        #pragma unroll
        for (int it = 0; it < 2; ++it) {
            int row = arow0 + it * 64;
            const float4* p = (const float4*)(x + (size_t)(rowBase + row) * HID + k0 + ac8);
            st[it * 2]     = p[0];
            st[it * 2 + 1] = p[1];
        }
    };
    auto stA = [&](uint32_t base, const float4* st) {
        #pragma unroll
        for (int it = 0; it < 2; ++it) {
            int row = arow0 + it * 64;
            float4 v0 = st[it * 2], v1 = st[it * 2 + 1];
            unsigned u0 = pack_bf16(v0.x, v0.y), u1 = pack_bf16(v0.z, v0.w);
            unsigned u2 = pack_bf16(v1.x, v1.y), u3 = pack_bf16(v1.z, v1.w);
            uint32_t off = (uint32_t)(row * 64 + ac8 * 2);
            STS128U(base + SWZ64(off), u0, u1, u2, u3);
        }
    };
    auto ldB = [&](int kc, uint4* st) {
        const int k0 = kc * BKG;
        #pragma unroll
        for (int it = 0; it < 2; ++it) {
            int task = tid + it * 256;
            int row = task >> 2;
            int e8  = (task & 3) * 8;
            st[it] = *(const uint4*)(g_w1b + (size_t)(colBase + row) * HID + k0 + e8);
        }
    };
    auto stB = [&](uint32_t base, const uint4* st) {
        #pragma unroll
        for (int it = 0; it < 2; ++it) {
            int task = tid + it * 256;
            int row = task >> 2;
            int c16 = (task & 3) * 16;
            uint32_t off = (uint32_t)(row * 64 + c16);
            STS128U(base + SWZ64(off), st[it].x, st[it].y, st[it].z, st[it].w);
        }
    };

    {
        float4 fa[4]; uint4 fb[2];
        ldA(0, fa); ldB(0, fb);
        stA(sa0, fa); stB(sb0, fb);
    }
    __syncthreads();

    float4 fa[4]; uint4 fb[2];
    for (int kt = 0; kt < NKT; ++kt) {
        const uint32_t aBase = (kt & 1) ? sa1 : sa0;
        const uint32_t bBase = (kt & 1) ? sb1 : sb0;
        if (kt < NKT - 1) { ldA(kt + 1, fa); ldB(kt + 1, fb); }

        #pragma unroll
        for (int ks = 0; ks < 2; ++ks) {
            uint32_t a[2][4];
            #pragma unroll
            for (int mi = 0; mi < 2; mi++)
                LDSM_X4(a[mi][0], a[mi][1], a[mi][2], a[mi][3], aBase + aOff[mi][ks]);
            #pragma unroll
            for (int nj = 0; nj < 4; nj++) {
                uint32_t b0, b1r, b2, b3;
                LDSM_X4(b0, b1r, b2, b3, bBase + bOff[nj][ks]);
                #pragma unroll
                for (int mi = 0; mi < 2; mi++) {
                    MMA_BF16(acc[mi][nj * 2],     a[mi][0], a[mi][1], a[mi][2], a[mi][3], b0, b1r);
                    MMA_BF16(acc[mi][nj * 2 + 1], a[mi][0], a[mi][1], a[mi][2], a[mi][3], b2, b3);
                }
            }
        }
        if (kt < NKT - 1) {
            const uint32_t aN = (kt & 1) ? sa0 : sa1;
            const uint32_t bN = (kt & 1) ? sb0 : sb1;
            stA(aN, fa); stB(bN, fb);
        }
        __syncthreads();
    }

    float rs00 = 0.f, rs01 = 0.f, rs10 = 0.f, rs11 = 0.f;
    #pragma unroll
    for (int mi = 0; mi < 2; mi++) {
        float s0 = 0.f, s1 = 0.f;
        #pragma unroll
        for (int ni = 0; ni < 8; ni++) {
            int c = nBase + ni * 8 + t * 2;
            s0 += fmaxf(acc[mi][ni][0] + b1s[c],     0.f) * w2s[c]
                + fmaxf(acc[mi][ni][1] + b1s[c + 1], 0.f) * w2s[c + 1];
            s1 += fmaxf(acc[mi][ni][2] + b1s[c],     0.f) * w2s[c]
                + fmaxf(acc[mi][ni][3] + b1s[c + 1], 0.f) * w2s[c + 1];
        }
        if (mi == 0) { rs00 = s0; rs01 = s1; } else { rs10 = s0; rs11 = s1; }
    }
    #pragma unroll
    for (int off = 1; off < 4; off <<= 1) {
        rs00 += __shfl_xor_sync(0xffffffff, rs00, off);
        rs01 += __shfl_xor_sync(0xffffffff, rs01, off);
        rs10 += __shfl_xor_sync(0xffffffff, rs10, off);
        rs11 += __shfl_xor_sync(0xffffffff, rs11, off);
    }
    if (t == 0) {
        atomicAdd(&s_part[mBase + g],      rs00);
        atomicAdd(&s_part[mBase + 8 + g],  rs01);
        atomicAdd(&s_part[mBase + 16 + g], rs10);
        atomicAdd(&s_part[mBase + 24 + g], rs11);
    }
    __syncthreads();
    if (tid < 128) atomicAdd(&g_att[rowBase + tid], s_part[tid]);
}

// ===========================================================================
// k_weights: per-batch softmax -> moments -> r -> w -> g_w (tiny, ~5us)
// ===========================================================================
__global__ __launch_bounds__(256)
void k_weights(const unsigned char* __restrict__ mask,
               const float* __restrict__ G,
               const float* __restrict__ mub) {
    __shared__ float smax[8], ssum[8][6];
    __shared__ float r_s[NB];

    const int b = blockIdx.x;
    const int tid = threadIdx.x, lane = tid & 31, warp = tid >> 5;

    float logit = -3.0e38f;
    if (tid < SEQ) {
        logit = g_att[b * SEQ + tid];
        if (mask[b * SEQ + tid]) logit = -1.0e9f;
    }
    float v = logit;
    #pragma unroll
    for (int off = 16; off > 0; off >>= 1) v = fmaxf(v, __shfl_xor_sync(0xffffffff, v, off));
    if (lane == 0) smax[warp] = v;
    __syncthreads();
    float mx = smax[0];
    #pragma unroll
    for (int w = 1; w < 8; w++) mx = fmaxf(mx, smax[w]);

    float e = (tid < SEQ) ? expf(logit - mx) : 0.f;
    float px = 0.f, py = 0.f;
    if (tid < SEQ) { px = (float)(tid / 14) * (1.f / 13.f); py = (float)(tid % 14) * (1.f / 13.f); }
    float s6[6] = { e, e * px, e * py, e * px * px, e * px * py, e * py * py };
    #pragma unroll
    for (int q = 0; q < 6; q++) {
        float sv = s6[q];
        #pragma unroll
        for (int off = 16; off > 0; off >>= 1) sv += __shfl_xor_sync(0xffffffff, sv, off);
        if (lane == 0) ssum[warp][q] = sv;
    }
    __syncthreads();
    float sums[6];
    #pragma unroll
    for (int q = 0; q < 6; q++) {
        float sv = 0.f;
        #pragma unroll
        for (int w = 0; w < 8; w++) sv += ssum[w][q];
        sums[q] = sv;
    }

    const float S   = sums[0];
    const float Mux = sums[1] / S, Muy = sums[2] / S;
    float S00 = sums[3] / S - Mux * Mux + 1e-6f;
    float S01 = sums[4] / S - Mux * Muy;
    float S11 = sums[5] / S - Muy * Muy + 1e-6f;
    float det = S00 * S11 - S01 * S01;
    float I00 = S11 / det, I01 = -S01 / det, I11 = S00 / det;
    float t0 = I00 * Mux + I01 * Muy;
    float t1 = I01 * Mux + I11 * Muy;
    float ds = I00 * I11 - I01 * I01;
    float R00 = I11 / ds, R01 = -I01 / ds, R11 = I00 / ds;
    float m0 = R00 * t0 + R01 * t1;
    float m1 = R01 * t0 + R11 * t1;
    float A00 = R00 + 1e-3f, A01 = R01, A11 = R11 + 1e-3f;
    float detA = A00 * A11 - A01 * A01;
    float Ai00 = A11 / detA, Ai01 = -A01 / detA, Ai11 = A00 / detA;
    float coef = 1.f / (6.2831853071795864769f * sqrtf(detA));

    if (tid < NB) {
        float d0 = m0 - mub[2 * tid];
        float d1 = m1 - mub[2 * tid + 1];
        float quad = d0 * (Ai00 * d0 + Ai01 * d1) + d1 * (Ai01 * d0 + Ai11 * d1);
        r_s[tid] = expf(-0.5f * quad) * coef;
    }
    __syncthreads();

    if (tid < SEQ) {
        float wv = 0.f;
        #pragma unroll 4
        for (int k = 0; k < NB; k++) wv += G[tid * NB + k] * r_s[k];
        g_w[b * SEQ + tid] = wv;
    }
}

// ===========================================================================
// k_ctx: pure streaming weighted sum over a batch chunk.
//   grid (4 slices, 256 batches); b = bOff + blockIdx.y
// ===========================================================================
__global__ __launch_bounds__(256)
void k_ctx(const float* __restrict__ x, int bOff) {
    __shared__ float w_s[SEQ];
    __shared__ float4 red[256];

    const int b = bOff + blockIdx.y, slice = blockIdx.x;
    const int tid = threadIdx.x;

    if (tid < SEQ) w_s[tid] = g_w[b * SEQ + tid];
    __syncthreads();

    const int h4 = tid & 63, nn = tid >> 6;
    const float4* xb = (const float4*)(x + (size_t)b * SEQ * HID) + slice * 64 + h4;
    float ax = 0.f, ay = 0.f, az = 0.f, aw = 0.f;
    #pragma unroll 7
    for (int n = nn; n < SEQ; n += 4) {
        float4 vv = __ldg(&xb[n * 256]);
        float wv = w_s[n];
        ax += wv * vv.x; ay += wv * vv.y; az += wv * vv.z; aw += wv * vv.w;
    }
    red[tid] = make_float4(ax, ay, az, aw);
    __syncthreads();
    if (tid < 64) {
        float4 a0 = red[tid], a1 = red[tid + 64], a2 = red[tid + 128], a3 = red[tid + 192];
        float4 o;
        o.x = a0.x + a1.x + a2.x + a3.x;
        o.y = a0.y + a1.y + a2.y + a3.y;
        o.z = a0.z + a1.z + a2.z + a3.z;
        o.w = a0.w + a1.w + a2.w + a3.w;
        ((float4*)(g_ctx + (size_t)b * HID + slice * 256))[tid] = o;
    }
}

// ===========================================================================
// k_out2: champion output GEMM over a row chunk (tf32, BM=64 BN=128).
//   grid (4 m-tiles, 16 n-tiles); mB = mOff + blockIdx.x*64
// ===========================================================================
#define BM2 64
#define BN2 128
#define XS2 20

__global__ __launch_bounds__(256, 2)
void k_out2(const float* __restrict__ Wm, const float* __restrict__ bm,
            float* __restrict__ out, int mOff) {
    __shared__ unsigned sa[2][BM2][XS2];
    __shared__ unsigned sbm[2][BN2][XS2];

    const int tid = threadIdx.x;
    const int mB = mOff + blockIdx.x * BM2, nB = blockIdx.y * BN2;
    const int lr = tid >> 2, lc = (tid & 3) * 4;
    const int warp = tid >> 5, lane = tid & 31;
    const int wm = warp & 1, wn = warp >> 1;
    const int mBase = wm * 32, nBase = wn * 32;
    const int g = lane >> 2, t = lane & 3;

    float acc[2][4][4];
    #pragma unroll
    for (int mi = 0; mi < 2; mi++)
        #pragma unroll
        for (int ni = 0; ni < 4; ni++)
            #pragma unroll
            for (int q = 0; q < 4; q++) acc[mi][ni][q] = 0.f;

    float4 pa, pb0, pb1;
    pa  = *(const float4*)&g_ctx[(size_t)(mB + lr) * HID + lc];
    pb0 = *(const float4*)&Wm  [(size_t)(nB + lr) * HID + lc];
    pb1 = *(const float4*)&Wm  [(size_t)(nB + lr + 64) * HID + lc];
    sa [0][lr][lc+0] = f2tf32(pa.x);  sa [0][lr][lc+1] = f2tf32(pa.y);
    sa [0][lr][lc+2] = f2tf32(pa.z);  sa [0][lr][lc+3] = f2tf32(pa.w);
    sbm[0][lr][lc+0] = f2tf32(pb0.x); sbm[0][lr][lc+1] = f2tf32(pb0.y);
    sbm[0][lr][lc+2] = f2tf32(pb0.z); sbm[0][lr][lc+3] = f2tf32(pb0.w);
    sbm[0][lr+64][lc+0] = f2tf32(pb1.x); sbm[0][lr+64][lc+1] = f2tf32(pb1.y);
    sbm[0][lr+64][lc+2] = f2tf32(pb1.z); sbm[0][lr+64][lc+3] = f2tf32(pb1.w);
    __syncthreads();

    const int NT = HID / 16;
    for (int kt = 0; kt < NT; ++kt) {
        const int buf = kt & 1;
        if (kt < NT - 1) {
            int k0 = (kt + 1) * 16;
            pa  = *(const float4*)&g_ctx[(size_t)(mB + lr) * HID + k0 + lc];
            pb0 = *(const float4*)&Wm  [(size_t)(nB + lr) * HID + k0 + lc];
            pb1 = *(const float4*)&Wm  [(size_t)(nB + lr + 64) * HID + k0 + lc];
        }
        #pragma unroll
        for (int ks = 0; ks < 2; ++ks) {
            const int k0s = ks * 8;
            unsigned a[2][4], bf[4][2];
            #pragma unroll
            for (int mi = 0; mi < 2; mi++) {
                int r0 = mBase + mi * 16 + g;
                a[mi][0] = sa[buf][r0    ][k0s + t];
                a[mi][1] = sa[buf][r0 + 8][k0s + t];
                a[mi][2] = sa[buf][r0    ][k0s + t + 4];
                a[mi][3] = sa[buf][r0 + 8][k0s + t + 4];
            }
            #pragma unroll
            for (int ni = 0; ni < 4; ni++) {
                int c0 = nBase + ni * 8 + g;
                bf[ni][0] = sbm[buf][c0][k0s + t];
                bf[ni][1] = sbm[buf][c0][k0s + t + 4];
            }
            #pragma unroll
            for (int mi = 0; mi < 2; mi++)
                #pragma unroll
                for (int ni = 0; ni < 4; ni++)
                    asm volatile(
                        "mma.sync.aligned.m16n8k8.row.col.f32.tf32.tf32.f32 "
                        "{%0,%1,%2,%3},{%4,%5,%6,%7},{%8,%9},{%0,%1,%2,%3};"
                        : "+f"(acc[mi][ni][0]), "+f"(acc[mi][ni][1]),
                          "+f"(acc[mi][ni][2]), "+f"(acc[mi][ni][3])
                        : "r"(a[mi][0]), "r"(a[mi][1]), "r"(a[mi][2]), "r"(a[mi][3]),
                          "r"(bf[ni][0]), "r"(bf[ni][1]));
        }
        if (kt < NT - 1) {
            int nb = buf ^ 1;
            sa [nb][lr][lc+0] = f2tf32(pa.x);  sa [nb][lr][lc+1] = f2tf32(pa.y);
            sa [nb][lr][lc+2] = f2tf32(pa.z);  sa [nb][lr][lc+3] = f2tf32(pa.w);
            sbm[nb][lr][lc+0] = f2tf32(pb0.x); sbm[nb][lr][lc+1] = f2tf32(pb0.y);
            sbm[nb][lr][lc+2] = f2tf32(pb0.z); sbm[nb][lr][lc+3] = f2tf32(pb0.w);
            sbm[nb][lr+64][lc+0] = f2tf32(pb1.x); sbm[nb][lr+64][lc+1] = f2tf32(pb1.y);
            sbm[nb][lr+64][lc+2] = f2tf32(pb1.z); sbm[nb][lr+64][lc+3] = f2tf32(pb1.w);
        }
        __syncthreads();
    }

    #pragma unroll
    for (int mi = 0; mi < 2; mi++)
        #pragma unroll
        for (int ni = 0; ni < 4; ni++) {
            int r0 = mB + mBase + mi * 16 + g;
            int c0 = nB + nBase + ni * 8 + t * 2;
            float bm0 = bm[c0], bm1 = bm[c0 + 1];
            out[(size_t)r0 * FOUT + c0]           = acc[mi][ni][0] + bm0;
            out[(size_t)r0 * FOUT + c0 + 1]       = acc[mi][ni][1] + bm1;
            out[(size_t)(r0 + 8) * FOUT + c0]     = acc[mi][ni][2] + bm0;
            out[(size_t)(r0 + 8) * FOUT + c0 + 1] = acc[mi][ni][3] + bm1;
        }
}

// ---------------------------------------------------------------------------
extern "C" void kernel_launch(void* const* d_in, const int* in_sizes, int n_in,
                              void* d_out, int out_size) {
    const float*         x   = (const float*)d_in[0];
    const unsigned char* xm  = (const unsigned char*)d_in[1];
    const float*         W1  = (const float*)d_in[2];
    const float*         b1  = (const float*)d_in[3];
    const float*         W2  = (const float*)d_in[4];
    // d_in[5] = b2: softmax-invariant, unused
    const float*         Wm  = (const float*)d_in[6];
    const float*         bm  = (const float*)d_in[7];
    const float*         G   = (const float*)d_in[8];
    const float*         mub = (const float*)d_in[9];
    float* out = (float*)d_out;

    // Fork-join side stream + events (created once; capture-compatible pattern
    // proven in round 10; events timing-disabled, no device allocations).
    static cudaStream_t s2 = nullptr;
    static cudaEvent_t ev0, ev1, evJ;
    if (!s2) {
        cudaStreamCreateWithFlags(&s2, cudaStreamNonBlocking);
        cudaEventCreateWithFlags(&ev0, cudaEventDisableTiming);
        cudaEventCreateWithFlags(&ev1, cudaEventDisableTiming);
        cudaEventCreateWithFlags(&evJ, cudaEventDisableTiming);
    }

    k_pre<<<613, 256>>>(W1);
    k_mlp_att<<<dim3(4, ROWS / 128), 256>>>(x, b1, W2);
    k_weights<<<BATCH, 256>>>(xm, G, mub);

    // ctx chunk 0 (batches 0..255), then out chunk 0 on s2 while ctx chunk 1 runs
    k_ctx<<<dim3(4, 256), 256>>>(x, 0);
    cudaEventRecord(ev0, 0);
    cudaStreamWaitEvent(s2, ev0, 0);
    k_out2<<<dim3(4, FOUT / BN2), 256, 0, s2>>>(Wm, bm, out, 0);

    k_ctx<<<dim3(4, 256), 256>>>(x, 256);
    cudaEventRecord(ev1, 0);
    cudaStreamWaitEvent(s2, ev1, 0);
    k_out2<<<dim3(4, FOUT / BN2), 256, 0, s2>>>(Wm, bm, out, 256);

    cudaEventRecord(evJ, s2);
    cudaStreamWaitEvent(0, evJ, 0);
}

// round 16
// speedup vs baseline: 1.0669x; 1.0669x over previous
#include <cuda_runtime.h>
#include <cuda_bf16.h>
#include <math.h>
#include <stdint.h>

#define BATCH 512
#define SEQ   196
#define HID   1024
#define MID   512
#define FOUT  2048
#define NB    100
#define ROWS  (BATCH*SEQ)   // 100352

// Scratch (device globals: no allocation allowed)
__device__ __align__(16) float g_att[ROWS];
__device__ __align__(16) float g_w[BATCH*SEQ];
__device__ __align__(16) float g_ctx[BATCH*HID];
__device__ __align__(16) __nv_bfloat16 g_w1b[MID*HID];

__device__ __forceinline__ unsigned pack_bf16(float lo, float hi) {
    unsigned r; asm("cvt.rn.bf16x2.f32 %0, %1, %2;" : "=r"(r) : "f"(hi), "f"(lo)); return r;
}
__device__ __forceinline__ unsigned f2tf32(float x) {
    unsigned y; asm("cvt.rna.tf32.f32 %0, %1;" : "=r"(y) : "f"(x)); return y;
}
__device__ __forceinline__ uint32_t smem_u32(const void* p) {
    uint32_t a;
    asm("{ .reg .u64 t; cvta.to.shared.u64 t, %1; cvt.u32.u64 %0, t; }" : "=r"(a) : "l"(p));
    return a;
}

// 64B-row swizzle (SW64): XOR bits [5:4] with bits [8:7]
#define SWZ64(o) ((o) ^ (((o) >> 3) & 0x30))

#define STS128U(addr, r0, r1, r2, r3) \
    asm volatile("st.shared.v4.b32 [%0], {%1,%2,%3,%4};" \
                 :: "r"(addr), "r"(r0), "r"(r1), "r"(r2), "r"(r3) : "memory")

#define LDSM_X4(r0, r1, r2, r3, addr) \
    asm volatile("ldmatrix.sync.aligned.m8n8.x4.shared.b16 {%0,%1,%2,%3}, [%4];" \
                 : "=r"(r0), "=r"(r1), "=r"(r2), "=r"(r3) : "r"(addr))

#define MMA_BF16(d, a0, a1, a2, a3, b0, b1) \
    asm volatile("mma.sync.aligned.m16n8k16.row.col.f32.bf16.bf16.f32 " \
                 "{%0,%1,%2,%3},{%4,%5,%6,%7},{%8,%9},{%0,%1,%2,%3};" \
                 : "+f"((d)[0]), "+f"((d)[1]), "+f"((d)[2]), "+f"((d)[3]) \
                 : "r"(a0), "r"(a1), "r"(a2), "r"(a3), "r"(b0), "r"(b1))

// ===========================================================================
// k_pre: cvt W1 -> bf16 (131072 float4) + zero g_att (25088 float4)
// ===========================================================================
__global__ void k_pre(const float* __restrict__ W1) {
    size_t i = (size_t)blockIdx.x * 256 + threadIdx.x;
    if (i < 131072) {
        float4 v = ((const float4*)W1)[i];
        ((uint2*)g_w1b)[i] = make_uint2(pack_bf16(v.x, v.y), pack_bf16(v.z, v.w));
    } else if (i < 131072 + 25088) {
        ((float4*)g_att)[i - 131072] = make_float4(0.f, 0.f, 0.f, 0.f);
    }
}

// ===========================================================================
// Kernel B: EXACT champion GEMM (measured ~357us).
//   BM=128, BN=128, BK=32, 256 threads, 8 warps of 32x64 tiles,
//   double-buffered SW64 smem, register-staged LDG->cvt->STS.
//   Fused relu/W2 row-sum epilogue -> atomicAdd g_att.
// ===========================================================================
#define BKG 32
#define NKT (HID/BKG)   // 32

__global__ __launch_bounds__(256, 2)
void k_mlp_att(const float* __restrict__ x,
               const float* __restrict__ b1,
               const float* __restrict__ W2) {
    __shared__ __align__(1024) char smA[2][128 * 64];
    __shared__ __align__(1024) char smB[2][128 * 64];
    __shared__ float b1s[128], w2s[128], s_part[128];

    const int tid  = threadIdx.x;
    const int lane = tid & 31;
    const int warp = tid >> 5;
    const int colBase = blockIdx.x * 128;     // n tile (fastest-varying)
    const int rowBase = blockIdx.y * 128;     // row tile

    const uint32_t sa0 = smem_u32(&smA[0][0]);
    const uint32_t sa1 = smem_u32(&smA[1][0]);
    const uint32_t sb0 = smem_u32(&smB[0][0]);
    const uint32_t sb1 = smem_u32(&smB[1][0]);

    if (tid < 128) {
        b1s[tid] = b1[colBase + tid];
        w2s[tid] = W2[colBase + tid];
        s_part[tid] = 0.f;
    }

    const int wm = warp & 3, wn = warp >> 2;
    const int mBase = wm * 32, nBase = wn * 64;
    const int g = lane >> 2, t = lane & 3;

    const int aRow = mBase + (lane & 15);
    const int aKb  = (lane >> 4) * 16;
    const int bRow = nBase + (lane & 7) + ((lane >> 4) * 8);
    const int bKb  = ((lane >> 3) & 1) * 16;

    uint32_t aOff[2][2], bOff[4][2];
    #pragma unroll
    for (int mi = 0; mi < 2; mi++)
        #pragma unroll
        for (int ks = 0; ks < 2; ks++)
            aOff[mi][ks] = SWZ64((uint32_t)((aRow + mi * 16) * 64 + ks * 32 + aKb));
    #pragma unroll
    for (int nj = 0; nj < 4; nj++)
        #pragma unroll
        for (int ks = 0; ks < 2; ks++)
            bOff[nj][ks] = SWZ64((uint32_t)((bRow + nj * 16) * 64 + ks * 32 + bKb));

    float acc[2][8][4];
    #pragma unroll
    for (int mi = 0; mi < 2; mi++)
        #pragma unroll
        for (int ni = 0; ni < 8; ni++)
            #pragma unroll
            for (int q = 0; q < 4; q++) acc[mi][ni][q] = 0.f;

    const int arow0 = tid >> 2;
    const int ac8   = (tid & 3) * 8;
    auto ldA = [&](int kc, float4* st) {
        const int k0 = kc * BKG;
        #pragma unroll
        for (int it = 0; it < 2; ++it) {
            int row = arow0 + it * 64;
            const float4* p = (const float4*)(x + (size_t)(rowBase + row) * HID + k0 + ac8);
            st[it * 2]     = p[0];
            st[it * 2 + 1] = p[1];
        }
    };
    auto stA = [&](uint32_t base, const float4* st) {
        #pragma unroll
        for (int it = 0; it < 2; ++it) {
            int row = arow0 + it * 64;
            float4 v0 = st[it * 2], v1 = st[it * 2 + 1];
            unsigned u0 = pack_bf16(v0.x, v0.y), u1 = pack_bf16(v0.z, v0.w);
            unsigned u2 = pack_bf16(v1.x, v1.y), u3 = pack_bf16(v1.z, v1.w);
            uint32_t off = (uint32_t)(row * 64 + ac8 * 2);
            STS128U(base + SWZ64(off), u0, u1, u2, u3);
        }
    };
    auto ldB = [&](int kc, uint4* st) {
        const int k0 = kc * BKG;
        #pragma unroll
        for (int it = 0; it < 2; ++it) {
            int task = tid + it * 256;
            int row = task >> 2;
            int e8  = (task & 3) * 8;
            st[it] = *(const uint4*)(g_w1b + (size_t)(colBase + row) * HID + k0 + e8);
        }
    };
    auto stB = [&](uint32_t base, const uint4* st) {
        #pragma unroll
        for (int it = 0; it < 2; ++it) {
            int task = tid + it * 256;
            int row = task >> 2;
            int c16 = (task & 3) * 16;
            uint32_t off = (uint32_t)(row * 64 + c16);
            STS128U(base + SWZ64(off), st[it].x, st[it].y, st[it].z, st[it].w);
        }
    };

    {
        float4 fa[4]; uint4 fb[2];
        ldA(0, fa); ldB(0, fb);
        stA(sa0, fa); stB(sb0, fb);
    }
    __syncthreads();

    float4 fa[4]; uint4 fb[2];
    for (int kt = 0; kt < NKT; ++kt) {
        const uint32_t aBase = (kt & 1) ? sa1 : sa0;
        const uint32_t bBase = (kt & 1) ? sb1 : sb0;
        if (kt < NKT - 1) { ldA(kt + 1, fa); ldB(kt + 1, fb); }

        #pragma unroll
        for (int ks = 0; ks < 2; ++ks) {
            uint32_t a[2][4];
            #pragma unroll
            for (int mi = 0; mi < 2; mi++)
                LDSM_X4(a[mi][0], a[mi][1], a[mi][2], a[mi][3], aBase + aOff[mi][ks]);
            #pragma unroll
            for (int nj = 0; nj < 4; nj++) {
                uint32_t b0, b1r, b2, b3;
                LDSM_X4(b0, b1r, b2, b3, bBase + bOff[nj][ks]);
                #pragma unroll
                for (int mi = 0; mi < 2; mi++) {
                    MMA_BF16(acc[mi][nj * 2],     a[mi][0], a[mi][1], a[mi][2], a[mi][3], b0, b1r);
                    MMA_BF16(acc[mi][nj * 2 + 1], a[mi][0], a[mi][1], a[mi][2], a[mi][3], b2, b3);
                }
            }
        }
        if (kt < NKT - 1) {
            const uint32_t aN = (kt & 1) ? sa0 : sa1;
            const uint32_t bN = (kt & 1) ? sb0 : sb1;
            stA(aN, fa); stB(bN, fb);
        }
        __syncthreads();
    }

    float rs00 = 0.f, rs01 = 0.f, rs10 = 0.f, rs11 = 0.f;
    #pragma unroll
    for (int mi = 0; mi < 2; mi++) {
        float s0 = 0.f, s1 = 0.f;
        #pragma unroll
        for (int ni = 0; ni < 8; ni++) {
            int c = nBase + ni * 8 + t * 2;
            s0 += fmaxf(acc[mi][ni][0] + b1s[c],     0.f) * w2s[c]
                + fmaxf(acc[mi][ni][1] + b1s[c + 1], 0.f) * w2s[c + 1];
            s1 += fmaxf(acc[mi][ni][2] + b1s[c],     0.f) * w2s[c]
                + fmaxf(acc[mi][ni][3] + b1s[c + 1], 0.f) * w2s[c + 1];
        }
        if (mi == 0) { rs00 = s0; rs01 = s1; } else { rs10 = s0; rs11 = s1; }
    }
    #pragma unroll
    for (int off = 1; off < 4; off <<= 1) {
        rs00 += __shfl_xor_sync(0xffffffff, rs00, off);
        rs01 += __shfl_xor_sync(0xffffffff, rs01, off);
        rs10 += __shfl_xor_sync(0xffffffff, rs10, off);
        rs11 += __shfl_xor_sync(0xffffffff, rs11, off);
    }
    if (t == 0) {
        atomicAdd(&s_part[mBase + g],      rs00);
        atomicAdd(&s_part[mBase + 8 + g],  rs01);
        atomicAdd(&s_part[mBase + 16 + g], rs10);
        atomicAdd(&s_part[mBase + 24 + g], rs11);
    }
    __syncthreads();
    if (tid < 128) atomicAdd(&g_att[rowBase + tid], s_part[tid]);
}

// ===========================================================================
// k_weights: per-batch softmax -> moments -> 2x2 algebra -> r -> w -> g_w.
// ===========================================================================
__global__ __launch_bounds__(256)
void k_weights(const unsigned char* __restrict__ mask,
               const float* __restrict__ G,
               const float* __restrict__ mub) {
    __shared__ float smax[8], ssum[8][6];
    __shared__ float r_s[NB];

    const int b = blockIdx.x;
    const int tid = threadIdx.x, lane = tid & 31, warp = tid >> 5;

    float logit = -3.0e38f;
    if (tid < SEQ) {
        logit = g_att[b * SEQ + tid];
        if (mask[b * SEQ + tid]) logit = -1.0e9f;
    }
    float v = logit;
    #pragma unroll
    for (int off = 16; off > 0; off >>= 1) v = fmaxf(v, __shfl_xor_sync(0xffffffff, v, off));
    if (lane == 0) smax[warp] = v;
    __syncthreads();
    float mx = smax[0];
    #pragma unroll
    for (int w = 1; w < 8; w++) mx = fmaxf(mx, smax[w]);

    float e = (tid < SEQ) ? expf(logit - mx) : 0.f;
    float px = 0.f, py = 0.f;
    if (tid < SEQ) { px = (float)(tid / 14) * (1.f / 13.f); py = (float)(tid % 14) * (1.f / 13.f); }
    float s6[6] = { e, e * px, e * py, e * px * px, e * px * py, e * py * py };
    #pragma unroll
    for (int q = 0; q < 6; q++) {
        float sv = s6[q];
        #pragma unroll
        for (int off = 16; off > 0; off >>= 1) sv += __shfl_xor_sync(0xffffffff, sv, off);
        if (lane == 0) ssum[warp][q] = sv;
    }
    __syncthreads();
    float sums[6];
    #pragma unroll
    for (int q = 0; q < 6; q++) {
        float sv = 0.f;
        #pragma unroll
        for (int w = 0; w < 8; w++) sv += ssum[w][q];
        sums[q] = sv;
    }

    const float S   = sums[0];
    const float Mux = sums[1] / S, Muy = sums[2] / S;
    float S00 = sums[3] / S - Mux * Mux + 1e-6f;
    float S01 = sums[4] / S - Mux * Muy;
    float S11 = sums[5] / S - Muy * Muy + 1e-6f;
    float det = S00 * S11 - S01 * S01;
    float I00 = S11 / det, I01 = -S01 / det, I11 = S00 / det;
    float t0 = I00 * Mux + I01 * Muy;
    float t1 = I01 * Mux + I11 * Muy;
    float ds = I00 * I11 - I01 * I01;
    float R00 = I11 / ds, R01 = -I01 / ds, R11 = I00 / ds;
    float m0 = R00 * t0 + R01 * t1;
    float m1 = R01 * t0 + R11 * t1;
    float A00 = R00 + 1e-3f, A01 = R01, A11 = R11 + 1e-3f;
    float detA = A00 * A11 - A01 * A01;
    float Ai00 = A11 / detA, Ai01 = -A01 / detA, Ai11 = A00 / detA;
    float coef = 1.f / (6.2831853071795864769f * sqrtf(detA));

    if (tid < NB) {
        float d0 = m0 - mub[2 * tid];
        float d1 = m1 - mub[2 * tid + 1];
        float quad = d0 * (Ai00 * d0 + Ai01 * d1) + d1 * (Ai01 * d0 + Ai11 * d1);
        r_s[tid] = expf(-0.5f * quad) * coef;
    }
    __syncthreads();

    if (tid < SEQ) {
        float wv = 0.f;
        #pragma unroll 4
        for (int k = 0; k < NB; k++) wv += G[tid * NB + k] * r_s[k];
        g_w[b * SEQ + tid] = wv;
    }
}

// ===========================================================================
// k_ctx2: pure streaming weighted sum, 512-h slices.
//   grid (2 slices, 512 batches), 256 threads. Each thread owns one h4
//   column (128 per slice) and n parity nn (2 threads per column).
// ===========================================================================
__global__ __launch_bounds__(256)
void k_ctx2(const float* __restrict__ x) {
    __shared__ float w_s[SEQ];
    __shared__ float4 red[256];

    const int b = blockIdx.y, slice = blockIdx.x;
    const int tid = threadIdx.x;

    if (tid < SEQ) w_s[tid] = g_w[b * SEQ + tid];
    __syncthreads();

    const int h4 = tid & 127;          // float4 column within 512-float slice
    const int nn = tid >> 7;           // 0 or 1
    const float4* xb = (const float4*)(x + (size_t)b * SEQ * HID) + slice * 128 + h4;
    float ax = 0.f, ay = 0.f, az = 0.f, aw = 0.f;
    #pragma unroll 7
    for (int n = nn; n < SEQ; n += 2) {
        float4 vv = __ldg(&xb[n * 256]);
        float wv = w_s[n];
        ax += wv * vv.x; ay += wv * vv.y; az += wv * vv.z; aw += wv * vv.w;
    }
    red[tid] = make_float4(ax, ay, az, aw);
    __syncthreads();
    if (tid < 128) {
        float4 a0 = red[tid], a1 = red[tid + 128];
        float4 o;
        o.x = a0.x + a1.x;
        o.y = a0.y + a1.y;
        o.z = a0.z + a1.z;
        o.w = a0.w + a1.w;
        ((float4*)(g_ctx + (size_t)b * HID + slice * 512))[tid] = o;
    }
}

// ===========================================================================
// k_out2: champion output GEMM (tf32 mma.sync, BM=64 BN=128, measured 45us)
// ===========================================================================
#define BM2 64
#define BN2 128
#define XS2 20

__global__ __launch_bounds__(256, 2)
void k_out2(const float* __restrict__ Wm, const float* __restrict__ bm,
            float* __restrict__ out) {
    __shared__ unsigned sa[2][BM2][XS2];
    __shared__ unsigned sbm[2][BN2][XS2];

    const int tid = threadIdx.x;
    const int mB = blockIdx.x * BM2, nB = blockIdx.y * BN2;
    const int lr = tid >> 2, lc = (tid & 3) * 4;
    const int warp = tid >> 5, lane = tid & 31;
    const int wm = warp & 1, wn = warp >> 1;
    const int mBase = wm * 32, nBase = wn * 32;
    const int g = lane >> 2, t = lane & 3;

    float acc[2][4][4];
    #pragma unroll
    for (int mi = 0; mi < 2; mi++)
        #pragma unroll
        for (int ni = 0; ni < 4; ni++)
            #pragma unroll
            for (int q = 0; q < 4; q++) acc[mi][ni][q] = 0.f;

    float4 pa, pb0, pb1;
    pa  = *(const float4*)&g_ctx[(size_t)(mB + lr) * HID + lc];
    pb0 = *(const float4*)&Wm  [(size_t)(nB + lr) * HID + lc];
    pb1 = *(const float4*)&Wm  [(size_t)(nB + lr + 64) * HID + lc];
    sa [0][lr][lc+0] = f2tf32(pa.x);  sa [0][lr][lc+1] = f2tf32(pa.y);
    sa [0][lr][lc+2] = f2tf32(pa.z);  sa [0][lr][lc+3] = f2tf32(pa.w);
    sbm[0][lr][lc+0] = f2tf32(pb0.x); sbm[0][lr][lc+1] = f2tf32(pb0.y);
    sbm[0][lr][lc+2] = f2tf32(pb0.z); sbm[0][lr][lc+3] = f2tf32(pb0.w);
    sbm[0][lr+64][lc+0] = f2tf32(pb1.x); sbm[0][lr+64][lc+1] = f2tf32(pb1.y);
    sbm[0][lr+64][lc+2] = f2tf32(pb1.z); sbm[0][lr+64][lc+3] = f2tf32(pb1.w);
    __syncthreads();

    const int NT = HID / 16;
    for (int kt = 0; kt < NT; ++kt) {
        const int buf = kt & 1;
        if (kt < NT - 1) {
            int k0 = (kt + 1) * 16;
            pa  = *(const float4*)&g_ctx[(size_t)(mB + lr) * HID + k0 + lc];
            pb0 = *(const float4*)&Wm  [(size_t)(nB + lr) * HID + k0 + lc];
            pb1 = *(const float4*)&Wm  [(size_t)(nB + lr + 64) * HID + k0 + lc];
        }
        #pragma unroll
        for (int ks = 0; ks < 2; ++ks) {
            const int k0s = ks * 8;
            unsigned a[2][4], bf[4][2];
            #pragma unroll
            for (int mi = 0; mi < 2; mi++) {
                int r0 = mBase + mi * 16 + g;
                a[mi][0] = sa[buf][r0    ][k0s + t];
                a[mi][1] = sa[buf][r0 + 8][k0s + t];
                a[mi][2] = sa[buf][r0    ][k0s + t + 4];
                a[mi][3] = sa[buf][r0 + 8][k0s + t + 4];
            }
            #pragma unroll
            for (int ni = 0; ni < 4; ni++) {
                int c0 = nBase + ni * 8 + g;
                bf[ni][0] = sbm[buf][c0][k0s + t];
                bf[ni][1] = sbm[buf][c0][k0s + t + 4];
            }
            #pragma unroll
            for (int mi = 0; mi < 2; mi++)
                #pragma unroll
                for (int ni = 0; ni < 4; ni++)
                    asm volatile(
                        "mma.sync.aligned.m16n8k8.row.col.f32.tf32.tf32.f32 "
                        "{%0,%1,%2,%3},{%4,%5,%6,%7},{%8,%9},{%0,%1,%2,%3};"
                        : "+f"(acc[mi][ni][0]), "+f"(acc[mi][ni][1]),
                          "+f"(acc[mi][ni][2]), "+f"(acc[mi][ni][3])
                        : "r"(a[mi][0]), "r"(a[mi][1]), "r"(a[mi][2]), "r"(a[mi][3]),
                          "r"(bf[ni][0]), "r"(bf[ni][1]));
        }
        if (kt < NT - 1) {
            int nb = buf ^ 1;
            sa [nb][lr][lc+0] = f2tf32(pa.x);  sa [nb][lr][lc+1] = f2tf32(pa.y);
            sa [nb][lr][lc+2] = f2tf32(pa.z);  sa [nb][lr][lc+3] = f2tf32(pa.w);
            sbm[nb][lr][lc+0] = f2tf32(pb0.x); sbm[nb][lr][lc+1] = f2tf32(pb0.y);
            sbm[nb][lr][lc+2] = f2tf32(pb0.z); sbm[nb][lr][lc+3] = f2tf32(pb0.w);
            sbm[nb][lr+64][lc+0] = f2tf32(pb1.x); sbm[nb][lr+64][lc+1] = f2tf32(pb1.y);
            sbm[nb][lr+64][lc+2] = f2tf32(pb1.z); sbm[nb][lr+64][lc+3] = f2tf32(pb1.w);
        }
        __syncthreads();
    }

    #pragma unroll
    for (int mi = 0; mi < 2; mi++)
        #pragma unroll
        for (int ni = 0; ni < 4; ni++) {
            int r0 = mB + mBase + mi * 16 + g;
            int c0 = nB + nBase + ni * 8 + t * 2;
            float bm0 = bm[c0], bm1 = bm[c0 + 1];
            out[(size_t)r0 * FOUT + c0]           = acc[mi][ni][0] + bm0;
            out[(size_t)r0 * FOUT + c0 + 1]       = acc[mi][ni][1] + bm1;
            out[(size_t)(r0 + 8) * FOUT + c0]     = acc[mi][ni][2] + bm0;
            out[(size_t)(r0 + 8) * FOUT + c0 + 1] = acc[mi][ni][3] + bm1;
        }
}

// ---------------------------------------------------------------------------
extern "C" void kernel_launch(void* const* d_in, const int* in_sizes, int n_in,
                              void* d_out, int out_size) {
    const float*         x   = (const float*)d_in[0];
    const unsigned char* xm  = (const unsigned char*)d_in[1];
    const float*         W1  = (const float*)d_in[2];
    const float*         b1  = (const float*)d_in[3];
    const float*         W2  = (const float*)d_in[4];
    // d_in[5] = b2: softmax-invariant, unused
    const float*         Wm  = (const float*)d_in[6];
    const float*         bm  = (const float*)d_in[7];
    const float*         G   = (const float*)d_in[8];
    const float*         mub = (const float*)d_in[9];
    float* out = (float*)d_out;

    k_pre<<<613, 256>>>(W1);
    k_mlp_att<<<dim3(4, ROWS / 128), 256>>>(x, b1, W2);
    k_weights<<<BATCH, 256>>>(xm, G, mub);
    k_ctx2<<<dim3(2, BATCH), 256>>>(x);
    k_out2<<<dim3(BATCH / BM2, FOUT / BN2), 256>>>(Wm, bm, out);
}

// round 17
// speedup vs baseline: 1.0908x; 1.0224x over previous
#include <cuda_runtime.h>
#include <cuda_bf16.h>
#include <math.h>
#include <stdint.h>

#define BATCH 512
#define SEQ   196
#define HID   1024
#define MID   512
#define FOUT  2048
#define NB    100
#define ROWS  (BATCH*SEQ)   // 100352

// Scratch (device globals: no allocation allowed)
__device__ __align__(16) float g_att[ROWS];
__device__ __align__(16) float g_w[BATCH*SEQ];
__device__ __align__(16) float g_ctx[BATCH*HID];
__device__ __align__(16) __nv_bfloat16 g_w1b[MID*HID];

__device__ __forceinline__ unsigned pack_bf16(float lo, float hi) {
    unsigned r; asm("cvt.rn.bf16x2.f32 %0, %1, %2;" : "=r"(r) : "f"(hi), "f"(lo)); return r;
}
__device__ __forceinline__ unsigned f2tf32(float x) {
    unsigned y; asm("cvt.rna.tf32.f32 %0, %1;" : "=r"(y) : "f"(x)); return y;
}
__device__ __forceinline__ uint32_t smem_u32(const void* p) {
    uint32_t a;
    asm("{ .reg .u64 t; cvta.to.shared.u64 t, %1; cvt.u32.u64 %0, t; }" : "=r"(a) : "l"(p));
    return a;
}

// 64B-row swizzle (SW64): XOR bits [5:4] with bits [8:7]
#define SWZ64(o) ((o) ^ (((o) >> 3) & 0x30))

#define STS128U(addr, r0, r1, r2, r3) \
    asm volatile("st.shared.v4.b32 [%0], {%1,%2,%3,%4};" \
                 :: "r"(addr), "r"(r0), "r"(r1), "r"(r2), "r"(r3) : "memory")

#define LDSM_X4(r0, r1, r2, r3, addr) \
    asm volatile("ldmatrix.sync.aligned.m8n8.x4.shared.b16 {%0,%1,%2,%3}, [%4];" \
                 : "=r"(r0), "=r"(r1), "=r"(r2), "=r"(r3) : "r"(addr))

#define MMA_BF16(d, a0, a1, a2, a3, b0, b1) \
    asm volatile("mma.sync.aligned.m16n8k16.row.col.f32.bf16.bf16.f32 " \
                 "{%0,%1,%2,%3},{%4,%5,%6,%7},{%8,%9},{%0,%1,%2,%3};" \
                 : "+f"((d)[0]), "+f"((d)[1]), "+f"((d)[2]), "+f"((d)[3]) \
                 : "r"(a0), "r"(a1), "r"(a2), "r"(a3), "r"(b0), "r"(b1))

// ===========================================================================
// k_pre: cvt W1 -> bf16 (131072 f4) + zero g_att (25088 f4) + out=bm (262144 f4)
// ===========================================================================
__global__ void k_pre(const float* __restrict__ W1,
                      const float* __restrict__ bm,
                      float* __restrict__ out) {
    size_t i = (size_t)blockIdx.x * 256 + threadIdx.x;
    if (i < 131072) {
        float4 v = ((const float4*)W1)[i];
        ((uint2*)g_w1b)[i] = make_uint2(pack_bf16(v.x, v.y), pack_bf16(v.z, v.w));
    } else if (i < 131072 + 25088) {
        ((float4*)g_att)[i - 131072] = make_float4(0.f, 0.f, 0.f, 0.f);
    } else if (i < 131072 + 25088 + 262144) {
        size_t j = i - (131072 + 25088);
        int f4 = (int)(j & 511);                    // FOUT/4 = 512
        ((float4*)out)[j] = ((const float4*)bm)[f4];
    }
}

// ===========================================================================
// Kernel B: EXACT champion GEMM (measured ~357us).
//   BM=128, BN=128, BK=32, 256 threads, 8 warps of 32x64 tiles,
//   double-buffered SW64 smem, register-staged LDG->cvt->STS.
//   Fused relu/W2 row-sum epilogue -> atomicAdd g_att.
// ===========================================================================
#define BKG 32
#define NKT (HID/BKG)   // 32

__global__ __launch_bounds__(256, 2)
void k_mlp_att(const float* __restrict__ x,
               const float* __restrict__ b1,
               const float* __restrict__ W2) {
    __shared__ __align__(1024) char smA[2][128 * 64];
    __shared__ __align__(1024) char smB[2][128 * 64];
    __shared__ float b1s[128], w2s[128], s_part[128];

    const int tid  = threadIdx.x;
    const int lane = tid & 31;
    const int warp = tid >> 5;
    const int colBase = blockIdx.x * 128;     // n tile (fastest-varying)
    const int rowBase = blockIdx.y * 128;     // row tile

    const uint32_t sa0 = smem_u32(&smA[0][0]);
    const uint32_t sa1 = smem_u32(&smA[1][0]);
    const uint32_t sb0 = smem_u32(&smB[0][0]);
    const uint32_t sb1 = smem_u32(&smB[1][0]);

    if (tid < 128) {
        b1s[tid] = b1[colBase + tid];
        w2s[tid] = W2[colBase + tid];
        s_part[tid] = 0.f;
    }

    const int wm = warp & 3, wn = warp >> 2;
    const int mBase = wm * 32, nBase = wn * 64;
    const int g = lane >> 2, t = lane & 3;

    const int aRow = mBase + (lane & 15);
    const int aKb  = (lane >> 4) * 16;
    const int bRow = nBase + (lane & 7) + ((lane >> 4) * 8);
    const int bKb  = ((lane >> 3) & 1) * 16;

    uint32_t aOff[2][2], bOff[4][2];
    #pragma unroll
    for (int mi = 0; mi < 2; mi++)
        #pragma unroll
        for (int ks = 0; ks < 2; ks++)
            aOff[mi][ks] = SWZ64((uint32_t)((aRow + mi * 16) * 64 + ks * 32 + aKb));
    #pragma unroll
    for (int nj = 0; nj < 4; nj++)
        #pragma unroll
        for (int ks = 0; ks < 2; ks++)
            bOff[nj][ks] = SWZ64((uint32_t)((bRow + nj * 16) * 64 + ks * 32 + bKb));

    float acc[2][8][4];
    #pragma unroll
    for (int mi = 0; mi < 2; mi++)
        #pragma unroll
        for (int ni = 0; ni < 8; ni++)
            #pragma unroll
            for (int q = 0; q < 4; q++) acc[mi][ni][q] = 0.f;

    const int arow0 = tid >> 2;
    const int ac8   = (tid & 3) * 8;
    auto ldA = [&](int kc, float4* st) {
        const int k0 = kc * BKG;
        #pragma unroll
        for (int it = 0; it < 2; ++it) {
            int row = arow0 + it * 64;
            const float4* p = (const float4*)(x + (size_t)(rowBase + row) * HID + k0 + ac8);
            st[it * 2]     = p[0];
            st[it * 2 + 1] = p[1];
        }
    };
    auto stA = [&](uint32_t base, const float4* st) {
        #pragma unroll
        for (int it = 0; it < 2; ++it) {
            int row = arow0 + it * 64;
            float4 v0 = st[it * 2], v1 = st[it * 2 + 1];
            unsigned u0 = pack_bf16(v0.x, v0.y), u1 = pack_bf16(v0.z, v0.w);
            unsigned u2 = pack_bf16(v1.x, v1.y), u3 = pack_bf16(v1.z, v1.w);
            uint32_t off = (uint32_t)(row * 64 + ac8 * 2);
            STS128U(base + SWZ64(off), u0, u1, u2, u3);
        }
    };
    auto ldB = [&](int kc, uint4* st) {
        const int k0 = kc * BKG;
        #pragma unroll
        for (int it = 0; it < 2; ++it) {
            int task = tid + it * 256;
            int row = task >> 2;
            int e8  = (task & 3) * 8;
            st[it] = *(const uint4*)(g_w1b + (size_t)(colBase + row) * HID + k0 + e8);
        }
    };
    auto stB = [&](uint32_t base, const uint4* st) {
        #pragma unroll
        for (int it = 0; it < 2; ++it) {
            int task = tid + it * 256;
            int row = task >> 2;
            int c16 = (task & 3) * 16;
            uint32_t off = (uint32_t)(row * 64 + c16);
            STS128U(base + SWZ64(off), st[it].x, st[it].y, st[it].z, st[it].w);
        }
    };

    {
        float4 fa[4]; uint4 fb[2];
        ldA(0, fa); ldB(0, fb);
        stA(sa0, fa); stB(sb0, fb);
    }
    __syncthreads();

    float4 fa[4]; uint4 fb[2];
    for (int kt = 0; kt < NKT; ++kt) {
        const uint32_t aBase = (kt & 1) ? sa1 : sa0;
        const uint32_t bBase = (kt & 1) ? sb1 : sb0;
        if (kt < NKT - 1) { ldA(kt + 1, fa); ldB(kt + 1, fb); }

        #pragma unroll
        for (int ks = 0; ks < 2; ++ks) {
            uint32_t a[2][4];
            #pragma unroll
            for (int mi = 0; mi < 2; mi++)
                LDSM_X4(a[mi][0], a[mi][1], a[mi][2], a[mi][3], aBase + aOff[mi][ks]);
            #pragma unroll
            for (int nj = 0; nj < 4; nj++) {
                uint32_t b0, b1r, b2, b3;
                LDSM_X4(b0, b1r, b2, b3, bBase + bOff[nj][ks]);
                #pragma unroll
                for (int mi = 0; mi < 2; mi++) {
                    MMA_BF16(acc[mi][nj * 2],     a[mi][0], a[mi][1], a[mi][2], a[mi][3], b0, b1r);
                    MMA_BF16(acc[mi][nj * 2 + 1], a[mi][0], a[mi][1], a[mi][2], a[mi][3], b2, b3);
                }
            }
        }
        if (kt < NKT - 1) {
            const uint32_t aN = (kt & 1) ? sa0 : sa1;
            const uint32_t bN = (kt & 1) ? sb0 : sb1;
            stA(aN, fa); stB(bN, fb);
        }
        __syncthreads();
    }

    float rs00 = 0.f, rs01 = 0.f, rs10 = 0.f, rs11 = 0.f;
    #pragma unroll
    for (int mi = 0; mi < 2; mi++) {
        float s0 = 0.f, s1 = 0.f;
        #pragma unroll
        for (int ni = 0; ni < 8; ni++) {
            int c = nBase + ni * 8 + t * 2;
            s0 += fmaxf(acc[mi][ni][0] + b1s[c],     0.f) * w2s[c]
                + fmaxf(acc[mi][ni][1] + b1s[c + 1], 0.f) * w2s[c + 1];
            s1 += fmaxf(acc[mi][ni][2] + b1s[c],     0.f) * w2s[c]
                + fmaxf(acc[mi][ni][3] + b1s[c + 1], 0.f) * w2s[c + 1];
        }
        if (mi == 0) { rs00 = s0; rs01 = s1; } else { rs10 = s0; rs11 = s1; }
    }
    #pragma unroll
    for (int off = 1; off < 4; off <<= 1) {
        rs00 += __shfl_xor_sync(0xffffffff, rs00, off);
        rs01 += __shfl_xor_sync(0xffffffff, rs01, off);
        rs10 += __shfl_xor_sync(0xffffffff, rs10, off);
        rs11 += __shfl_xor_sync(0xffffffff, rs11, off);
    }
    if (t == 0) {
        atomicAdd(&s_part[mBase + g],      rs00);
        atomicAdd(&s_part[mBase + 8 + g],  rs01);
        atomicAdd(&s_part[mBase + 16 + g], rs10);
        atomicAdd(&s_part[mBase + 24 + g], rs11);
    }
    __syncthreads();
    if (tid < 128) atomicAdd(&g_att[rowBase + tid], s_part[tid]);
}

// ===========================================================================
// k_weights: per-batch softmax -> moments -> 2x2 algebra -> r -> w -> g_w.
// ===========================================================================
__global__ __launch_bounds__(256)
void k_weights(const unsigned char* __restrict__ mask,
               const float* __restrict__ G,
               const float* __restrict__ mub) {
    __shared__ float smax[8], ssum[8][6];
    __shared__ float r_s[NB];

    const int b = blockIdx.x;
    const int tid = threadIdx.x, lane = tid & 31, warp = tid >> 5;

    float logit = -3.0e38f;
    if (tid < SEQ) {
        logit = g_att[b * SEQ + tid];
        if (mask[b * SEQ + tid]) logit = -1.0e9f;
    }
    float v = logit;
    #pragma unroll
    for (int off = 16; off > 0; off >>= 1) v = fmaxf(v, __shfl_xor_sync(0xffffffff, v, off));
    if (lane == 0) smax[warp] = v;
    __syncthreads();
    float mx = smax[0];
    #pragma unroll
    for (int w = 1; w < 8; w++) mx = fmaxf(mx, smax[w]);

    float e = (tid < SEQ) ? expf(logit - mx) : 0.f;
    float px = 0.f, py = 0.f;
    if (tid < SEQ) { px = (float)(tid / 14) * (1.f / 13.f); py = (float)(tid % 14) * (1.f / 13.f); }
    float s6[6] = { e, e * px, e * py, e * px * px, e * px * py, e * py * py };
    #pragma unroll
    for (int q = 0; q < 6; q++) {
        float sv = s6[q];
        #pragma unroll
        for (int off = 16; off > 0; off >>= 1) sv += __shfl_xor_sync(0xffffffff, sv, off);
        if (lane == 0) ssum[warp][q] = sv;
    }
    __syncthreads();
    float sums[6];
    #pragma unroll
    for (int q = 0; q < 6; q++) {
        float sv = 0.f;
        #pragma unroll
        for (int w = 0; w < 8; w++) sv += ssum[w][q];
        sums[q] = sv;
    }

    const float S   = sums[0];
    const float Mux = sums[1] / S, Muy = sums[2] / S;
    float S00 = sums[3] / S - Mux * Mux + 1e-6f;
    float S01 = sums[4] / S - Mux * Muy;
    float S11 = sums[5] / S - Muy * Muy + 1e-6f;
    float det = S00 * S11 - S01 * S01;
    float I00 = S11 / det, I01 = -S01 / det, I11 = S00 / det;
    float t0 = I00 * Mux + I01 * Muy;
    float t1 = I01 * Mux + I11 * Muy;
    float ds = I00 * I11 - I01 * I01;
    float R00 = I11 / ds, R01 = -I01 / ds, R11 = I00 / ds;
    float m0 = R00 * t0 + R01 * t1;
    float m1 = R01 * t0 + R11 * t1;
    float A00 = R00 + 1e-3f, A01 = R01, A11 = R11 + 1e-3f;
    float detA = A00 * A11 - A01 * A01;
    float Ai00 = A11 / detA, Ai01 = -A01 / detA, Ai11 = A00 / detA;
    float coef = 1.f / (6.2831853071795864769f * sqrtf(detA));

    if (tid < NB) {
        float d0 = m0 - mub[2 * tid];
        float d1 = m1 - mub[2 * tid + 1];
        float quad = d0 * (Ai00 * d0 + Ai01 * d1) + d1 * (Ai01 * d0 + Ai11 * d1);
        r_s[tid] = expf(-0.5f * quad) * coef;
    }
    __syncthreads();

    if (tid < SEQ) {
        float wv = 0.f;
        #pragma unroll 4
        for (int k = 0; k < NB; k++) wv += G[tid * NB + k] * r_s[k];
        g_w[b * SEQ + tid] = wv;
    }
}

// ===========================================================================
// k_ctx: pure streaming weighted sum (round-14 champion shape: 4 slices).
//   grid (4 slices, 512 batches), 256 threads.
// ===========================================================================
__global__ __launch_bounds__(256)
void k_ctx(const float* __restrict__ x) {
    __shared__ float w_s[SEQ];
    __shared__ float4 red[256];

    const int b = blockIdx.y, slice = blockIdx.x;
    const int tid = threadIdx.x;

    if (tid < SEQ) w_s[tid] = g_w[b * SEQ + tid];
    __syncthreads();

    const int h4 = tid & 63, nn = tid >> 6;
    const float4* xb = (const float4*)(x + (size_t)b * SEQ * HID) + slice * 64 + h4;
    float ax = 0.f, ay = 0.f, az = 0.f, aw = 0.f;
    #pragma unroll 7
    for (int n = nn; n < SEQ; n += 4) {
        float4 vv = __ldg(&xb[n * 256]);
        float wv = w_s[n];
        ax += wv * vv.x; ay += wv * vv.y; az += wv * vv.z; aw += wv * vv.w;
    }
    red[tid] = make_float4(ax, ay, az, aw);
    __syncthreads();
    if (tid < 64) {
        float4 a0 = red[tid], a1 = red[tid + 64], a2 = red[tid + 128], a3 = red[tid + 192];
        float4 o;
        o.x = a0.x + a1.x + a2.x + a3.x;
        o.y = a0.y + a1.y + a2.y + a3.y;
        o.z = a0.z + a1.z + a2.z + a3.z;
        o.w = a0.w + a1.w + a2.w + a3.w;
        ((float4*)(g_ctx + (size_t)b * HID + slice * 256))[tid] = o;
    }
}

// ===========================================================================
// k_out5: out += ctx @ Wm^T (tf32 mma.sync, BM=64 BN=128, SPLIT-K=2).
//   grid (8, 16, 2) = 256 CTAs; each kk handles K range [kk*512, kk*512+512).
//   Partials combined via atomicAdd into out (pre-initialized with bm).
// ===========================================================================
#define BM2 64
#define BN2 128
#define XS2 20
#define NT5 32          // (HID/2)/16

__global__ __launch_bounds__(256, 2)
void k_out5(const float* __restrict__ Wm, float* __restrict__ out) {
    __shared__ unsigned sa[2][BM2][XS2];
    __shared__ unsigned sbm[2][BN2][XS2];

    const int tid = threadIdx.x;
    const int mB = blockIdx.x * BM2, nB = blockIdx.y * BN2;
    const int kBase = blockIdx.z * (HID / 2);
    const int lr = tid >> 2, lc = (tid & 3) * 4;
    const int warp = tid >> 5, lane = tid & 31;
    const int wm = warp & 1, wn = warp >> 1;
    const int mBase = wm * 32, nBase = wn * 32;
    const int g = lane >> 2, t = lane & 3;

    float acc[2][4][4];
    #pragma unroll
    for (int mi = 0; mi < 2; mi++)
        #pragma unroll
        for (int ni = 0; ni < 4; ni++)
            #pragma unroll
            for (int q = 0; q < 4; q++) acc[mi][ni][q] = 0.f;

    float4 pa, pb0, pb1;
    pa  = *(const float4*)&g_ctx[(size_t)(mB + lr) * HID + kBase + lc];
    pb0 = *(const float4*)&Wm  [(size_t)(nB + lr) * HID + kBase + lc];
    pb1 = *(const float4*)&Wm  [(size_t)(nB + lr + 64) * HID + kBase + lc];
    sa [0][lr][lc+0] = f2tf32(pa.x);  sa [0][lr][lc+1] = f2tf32(pa.y);
    sa [0][lr][lc+2] = f2tf32(pa.z);  sa [0][lr][lc+3] = f2tf32(pa.w);
    sbm[0][lr][lc+0] = f2tf32(pb0.x); sbm[0][lr][lc+1] = f2tf32(pb0.y);
    sbm[0][lr][lc+2] = f2tf32(pb0.z); sbm[0][lr][lc+3] = f2tf32(pb0.w);
    sbm[0][lr+64][lc+0] = f2tf32(pb1.x); sbm[0][lr+64][lc+1] = f2tf32(pb1.y);
    sbm[0][lr+64][lc+2] = f2tf32(pb1.z); sbm[0][lr+64][lc+3] = f2tf32(pb1.w);
    __syncthreads();

    for (int kt = 0; kt < NT5; ++kt) {
        const int buf = kt & 1;
        if (kt < NT5 - 1) {
            int k0 = kBase + (kt + 1) * 16;
            pa  = *(const float4*)&g_ctx[(size_t)(mB + lr) * HID + k0 + lc];
            pb0 = *(const float4*)&Wm  [(size_t)(nB + lr) * HID + k0 + lc];
            pb1 = *(const float4*)&Wm  [(size_t)(nB + lr + 64) * HID + k0 + lc];
        }
        #pragma unroll
        for (int ks = 0; ks < 2; ++ks) {
            const int k0s = ks * 8;
            unsigned a[2][4], bf[4][2];
            #pragma unroll
            for (int mi = 0; mi < 2; mi++) {
                int r0 = mBase + mi * 16 + g;
                a[mi][0] = sa[buf][r0    ][k0s + t];
                a[mi][1] = sa[buf][r0 + 8][k0s + t];
                a[mi][2] = sa[buf][r0    ][k0s + t + 4];
                a[mi][3] = sa[buf][r0 + 8][k0s + t + 4];
            }
            #pragma unroll
            for (int ni = 0; ni < 4; ni++) {
                int c0 = nBase + ni * 8 + g;
                bf[ni][0] = sbm[buf][c0][k0s + t];
                bf[ni][1] = sbm[buf][c0][k0s + t + 4];
            }
            #pragma unroll
            for (int mi = 0; mi < 2; mi++)
                #pragma unroll
                for (int ni = 0; ni < 4; ni++)
                    asm volatile(
                        "mma.sync.aligned.m16n8k8.row.col.f32.tf32.tf32.f32 "
                        "{%0,%1,%2,%3},{%4,%5,%6,%7},{%8,%9},{%0,%1,%2,%3};"
                        : "+f"(acc[mi][ni][0]), "+f"(acc[mi][ni][1]),
                          "+f"(acc[mi][ni][2]), "+f"(acc[mi][ni][3])
                        : "r"(a[mi][0]), "r"(a[mi][1]), "r"(a[mi][2]), "r"(a[mi][3]),
                          "r"(bf[ni][0]), "r"(bf[ni][1]));
        }
        if (kt < NT5 - 1) {
            int nb = buf ^ 1;
            sa [nb][lr][lc+0] = f2tf32(pa.x);  sa [nb][lr][lc+1] = f2tf32(pa.y);
            sa [nb][lr][lc+2] = f2tf32(pa.z);  sa [nb][lr][lc+3] = f2tf32(pa.w);
            sbm[nb][lr][lc+0] = f2tf32(pb0.x); sbm[nb][lr][lc+1] = f2tf32(pb0.y);
            sbm[nb][lr][lc+2] = f2tf32(pb0.z); sbm[nb][lr][lc+3] = f2tf32(pb0.w);
            sbm[nb][lr+64][lc+0] = f2tf32(pb1.x); sbm[nb][lr+64][lc+1] = f2tf32(pb1.y);
            sbm[nb][lr+64][lc+2] = f2tf32(pb1.z); sbm[nb][lr+64][lc+3] = f2tf32(pb1.w);
        }
        __syncthreads();
    }

    #pragma unroll
    for (int mi = 0; mi < 2; mi++)
        #pragma unroll
        for (int ni = 0; ni < 4; ni++) {
            int r0 = mB + mBase + mi * 16 + g;
            int c0 = nB + nBase + ni * 8 + t * 2;
            atomicAdd(&out[(size_t)r0 * FOUT + c0],           acc[mi][ni][0]);
            atomicAdd(&out[(size_t)r0 * FOUT + c0 + 1],       acc[mi][ni][1]);
            atomicAdd(&out[(size_t)(r0 + 8) * FOUT + c0],     acc[mi][ni][2]);
            atomicAdd(&out[(size_t)(r0 + 8) * FOUT + c0 + 1], acc[mi][ni][3]);
        }
}

// ---------------------------------------------------------------------------
extern "C" void kernel_launch(void* const* d_in, const int* in_sizes, int n_in,
                              void* d_out, int out_size) {
    const float*         x   = (const float*)d_in[0];
    const unsigned char* xm  = (const unsigned char*)d_in[1];
    const float*         W1  = (const float*)d_in[2];
    const float*         b1  = (const float*)d_in[3];
    const float*         W2  = (const float*)d_in[4];
    // d_in[5] = b2: softmax-invariant, unused
    const float*         Wm  = (const float*)d_in[6];
    const float*         bm  = (const float*)d_in[7];
    const float*         G   = (const float*)d_in[8];
    const float*         mub = (const float*)d_in[9];
    float* out = (float*)d_out;

    k_pre<<<1634, 256>>>(W1, bm, out);                    // 418304 tasks
    k_mlp_att<<<dim3(4, ROWS / 128), 256>>>(x, b1, W2);
    k_weights<<<BATCH, 256>>>(xm, G, mub);
    k_ctx<<<dim3(4, BATCH), 256>>>(x);
    k_out5<<<dim3(BATCH / BM2, FOUT / BN2, 2), 256>>>(Wm, out);
}